// round 2
// baseline (speedup 1.0000x reference)
#include <cuda_runtime.h>
#include <cuda_bf16.h>
#include <math.h>

// ---------------------------------------------------------------------------
// Self_Correlation_Per_tt : x[8,64,64,64] fp32 -> out[8,115,24,24] fp32
//
// Stage 1 (per b,c):  patches A[P=3249, 64] (8x8 kernel windows), L2-normalize
//   columns over P, corr = A^T A / P  -> [64,64]. For each column n, sort the
//   64 values over m descending, pick ranks {1,9,16,24,32,40,48,55,63}
//   -> pool2[b,c,p] with p = r*64 + n  (576 values).
// Stage 2 (per b):    L2-normalize pool2 over c, corr2 = X^T X / 64
//   [576,576]; for each column q sort over p descending, pick 115 ranks
//   round(linspace(1,575,115)) -> out[b, r, q(24x24)].
// ---------------------------------------------------------------------------

#define IMS 65          // padded shared row stride (floats) for 64-wide image
#define N_BC 512        // 8 * 64
#define NP 3249         // 57*57 patch positions
#define POOL_P 576      // 9*64
#define OUT_R 115

__device__ __align__(16) float g_pool2t[8 * POOL_P * 64];  // [b][p][c]
__device__ float g_invn[8 * POOL_P];                        // 1/max(||.||,eps)

__constant__ int c_ranks2[9] = {1, 9, 16, 24, 32, 40, 48, 55, 63};

// ---------------------------------------------------------------------------
// Stage 1: one block per (b,c). 256 threads.
// ---------------------------------------------------------------------------
__global__ __launch_bounds__(256) void stage1_kernel(const float* __restrict__ x)
{
    __shared__ float s_img[64 * IMS];
    __shared__ float s_corr[64 * IMS];
    __shared__ float s_norm[64];

    const int tid = threadIdx.x;
    const int blk = blockIdx.x;            // b*64 + c
    const int bb  = blk >> 6;
    const int cc  = blk & 63;

    // load 64x64 image into padded shared
    const float* src = x + (size_t)blk * 4096;
    for (int i = tid; i < 4096; i += 256)
        s_img[(i >> 6) * IMS + (i & 63)] = src[i];
    __syncthreads();

    // ---- Gram: 16x16 threads, each a 4x4 tile of the 64x64 output ----
    const int ty = tid >> 4, tx = tid & 15;
    const int m0 = ty * 4,   n0 = tx * 4;
    const int kim = ty >> 1, kjm = (ty & 1) * 4;   // m = ki*8+kj, 4 consecutive kj
    const int kin = tx >> 1, kjn = (tx & 1) * 4;

    float acc[4][4];
#pragma unroll
    for (int i = 0; i < 4; ++i)
#pragma unroll
        for (int j = 0; j < 4; ++j) acc[i][j] = 0.0f;

    for (int oi = 0; oi < 57; ++oi) {
        const float* rm = s_img + (oi + kim) * IMS + kjm;
        const float* rn = s_img + (oi + kin) * IMS + kjn;
        float am[4], an[4];
#pragma unroll
        for (int t = 0; t < 4; ++t) { am[t] = rm[t]; an[t] = rn[t]; }
#pragma unroll
        for (int oj = 0; oj < 57; ++oj) {
#pragma unroll
            for (int i = 0; i < 4; ++i)
#pragma unroll
                for (int j = 0; j < 4; ++j)
                    acc[i][j] = fmaf(am[i], an[j], acc[i][j]);
            if (oj < 56) {   // rolling window: 2 LDS per 16 FMA
#pragma unroll
                for (int t = 0; t < 3; ++t) { am[t] = am[t + 1]; an[t] = an[t + 1]; }
                am[3] = rm[oj + 4];
                an[3] = rn[oj + 4];
            }
        }
    }

#pragma unroll
    for (int i = 0; i < 4; ++i)
#pragma unroll
        for (int j = 0; j < 4; ++j)
            s_corr[(m0 + i) * IMS + (n0 + j)] = acc[i][j];
    __syncthreads();

    // column norms from the diagonal
    if (tid < 64) {
        float g = s_corr[tid * IMS + tid];
        s_norm[tid] = 1.0f / fmaxf(sqrtf(g), 1e-12f);
    }
    __syncthreads();

    // corr[m][n] = G * invn_m * invn_n / P
#pragma unroll
    for (int i = 0; i < 4; ++i)
#pragma unroll
        for (int j = 0; j < 4; ++j)
            s_corr[(m0 + i) * IMS + (n0 + j)] =
                acc[i][j] * s_norm[m0 + i] * s_norm[n0 + j] * (1.0f / (float)NP);
    __syncthreads();

    // ---- rank-by-count selection: for each column n, descending rank of
    //      each m (ties broken by index -> exact permutation). 4 threads/col.
    const int n   = tid & 63;
    const int sub = tid >> 6;      // 0..3, each handles 16 m's
    for (int mi = 0; mi < 16; ++mi) {
        const int m = sub * 16 + mi;
        const float v = s_corr[m * IMS + n];
        int rank = 0;
#pragma unroll 8
        for (int mm = 0; mm < 64; ++mm) {
            float w = s_corr[mm * IMS + n];
            rank += (w > v) || (w == v && mm < m);
        }
#pragma unroll
        for (int r = 0; r < 9; ++r)
            if (rank == c_ranks2[r])
                g_pool2t[((size_t)bb * POOL_P + (r * 64 + n)) * 64 + cc] = v;
    }
}

// ---------------------------------------------------------------------------
// Stage 2a: per-(b,p) inverse norms over c.
// ---------------------------------------------------------------------------
__global__ void invn_kernel()
{
    int idx = blockIdx.x * blockDim.x + threadIdx.x;
    if (idx >= 8 * POOL_P) return;
    const float4* v = (const float4*)(g_pool2t + (size_t)idx * 64);
    float s = 0.0f;
#pragma unroll
    for (int i = 0; i < 16; ++i) {
        float4 t = v[i];
        s += t.x * t.x + t.y * t.y + t.z * t.z + t.w * t.w;
    }
    g_invn[idx] = 1.0f / fmaxf(sqrtf(s), 1e-12f);
}

// ---------------------------------------------------------------------------
// Stage 2b: one block per (b, group-of-4 q). Compute 4 columns of corr2,
// bitonic-sort each (descending, padded to 1024), emit 115 ranked values.
// ---------------------------------------------------------------------------
__global__ __launch_bounds__(256) void stage2_kernel(float* __restrict__ out)
{
    __shared__ float s_xq[4][64];
    __shared__ float s_cols[4][POOL_P];
    __shared__ float s_buf[1024];

    const int tid = threadIdx.x;
    const int b   = blockIdx.x / 144;
    const int q0  = (blockIdx.x % 144) * 4;

    {   // load 4 q vectors (256 threads = 4*64 exactly)
        int k = tid >> 6, c = tid & 63;
        s_xq[k][c] = g_pool2t[((size_t)b * POOL_P + q0 + k) * 64 + c];
    }
    __syncthreads();

    // 4 dot products per row p (invn_p folded in; invn_q / 64 applied after
    // the sort — positive scale preserves order)
    for (int p = tid; p < POOL_P; p += 256) {
        const float4* xp = (const float4*)(g_pool2t + ((size_t)b * POOL_P + p) * 64);
        float d0 = 0.f, d1 = 0.f, d2 = 0.f, d3 = 0.f;
#pragma unroll
        for (int c4 = 0; c4 < 16; ++c4) {
            float4 v = xp[c4];
            int c = c4 * 4;
            d0 = fmaf(v.x, s_xq[0][c], d0); d0 = fmaf(v.y, s_xq[0][c+1], d0);
            d0 = fmaf(v.z, s_xq[0][c+2], d0); d0 = fmaf(v.w, s_xq[0][c+3], d0);
            d1 = fmaf(v.x, s_xq[1][c], d1); d1 = fmaf(v.y, s_xq[1][c+1], d1);
            d1 = fmaf(v.z, s_xq[1][c+2], d1); d1 = fmaf(v.w, s_xq[1][c+3], d1);
            d2 = fmaf(v.x, s_xq[2][c], d2); d2 = fmaf(v.y, s_xq[2][c+1], d2);
            d2 = fmaf(v.z, s_xq[2][c+2], d2); d2 = fmaf(v.w, s_xq[2][c+3], d2);
            d3 = fmaf(v.x, s_xq[3][c], d3); d3 = fmaf(v.y, s_xq[3][c+1], d3);
            d3 = fmaf(v.z, s_xq[3][c+2], d3); d3 = fmaf(v.w, s_xq[3][c+3], d3);
        }
        const float ip = g_invn[b * POOL_P + p];
        s_cols[0][p] = d0 * ip;
        s_cols[1][p] = d1 * ip;
        s_cols[2][p] = d2 * ip;
        s_cols[3][p] = d3 * ip;
    }

    const double step = 574.0 / 114.0;   // np.linspace(1, 575, 115) step
    for (int k = 0; k < 4; ++k) {
        __syncthreads();
        for (int i = tid; i < 1024; i += 256)
            s_buf[i] = (i < POOL_P) ? s_cols[k][i] : -3.402823466e38f;
        __syncthreads();

        // bitonic sort, descending
        for (int kk = 2; kk <= 1024; kk <<= 1) {
            for (int j = kk >> 1; j > 0; j >>= 1) {
                for (int i = tid; i < 1024; i += 256) {
                    int ixj = i ^ j;
                    if (ixj > i) {
                        float a = s_buf[i], c2 = s_buf[ixj];
                        bool dsc = (i & kk) == 0;
                        if (dsc ? (a < c2) : (a > c2)) {
                            s_buf[i] = c2;
                            s_buf[ixj] = a;
                        }
                    }
                }
                __syncthreads();
            }
        }

        if (tid < OUT_R) {
            int rank = (int)rint(1.0 + (double)tid * step);  // half-even == np.round
            float invq = g_invn[b * POOL_P + q0 + k];
            out[((size_t)b * OUT_R + tid) * POOL_P + (q0 + k)] =
                s_buf[rank] * invq * (1.0f / 64.0f);
        }
    }
}

// ---------------------------------------------------------------------------
extern "C" void kernel_launch(void* const* d_in, const int* in_sizes, int n_in,
                              void* d_out, int out_size)
{
    const float* x = (const float*)d_in[0];
    float* out = (float*)d_out;

    stage1_kernel<<<N_BC, 256>>>(x);
    invn_kernel<<<(8 * POOL_P + 255) / 256, 256>>>();
    stage2_kernel<<<8 * 144, 256>>>(out);
}

// round 3
// speedup vs baseline: 1.5363x; 1.5363x over previous
#include <cuda_runtime.h>
#include <cuda_bf16.h>
#include <math.h>

// ---------------------------------------------------------------------------
// Self_Correlation_Per_tt : x[8,64,64,64] fp32 -> out[8,115,24,24] fp32
// ---------------------------------------------------------------------------

#define IMS 65          // padded shared row stride (floats)
#define N_BC 512        // 8 * 64
#define NP 3249         // 57*57 patch positions
#define POOL_P 576      // 9*64
#define OUT_R 115

__device__ __align__(16) float g_pool2t[8 * POOL_P * 64];  // [b][p][c]
__device__ float g_invn[8 * POOL_P];                        // 1/max(||.||,eps)

__constant__ int c_ranks2[9] = {1, 9, 16, 24, 32, 40, 48, 55, 63};

// ---------------------------------------------------------------------------
// Stage 1: one block per (b,c). 256 threads, 4x4 output tile each.
// Inner loop fully unrolled with an 8-wide circular register window: no MOVs.
// ---------------------------------------------------------------------------
__global__ __launch_bounds__(256) void stage1_kernel(const float* __restrict__ x)
{
    __shared__ float s_img[64 * IMS];
    __shared__ float s_corr[64 * IMS];
    __shared__ float s_norm[64];

    const int tid = threadIdx.x;
    const int blk = blockIdx.x;            // b*64 + c
    const int bb  = blk >> 6;
    const int cc  = blk & 63;

    const float* src = x + (size_t)blk * 4096;
    for (int i = tid; i < 4096; i += 256)
        s_img[(i >> 6) * IMS + (i & 63)] = src[i];
    __syncthreads();

    const int ty = tid >> 4, tx = tid & 15;
    const int m0 = ty * 4,   n0 = tx * 4;
    const int kim = ty >> 1, kjm = (ty & 1) * 4;   // m = ki*8+kj
    const int kin = tx >> 1, kjn = (tx & 1) * 4;

    float acc[4][4];
#pragma unroll
    for (int i = 0; i < 4; ++i)
#pragma unroll
        for (int j = 0; j < 4; ++j) acc[i][j] = 0.0f;

    for (int oi = 0; oi < 57; ++oi) {
        const float* rm = s_img + (oi + kim) * IMS + kjm;
        const float* rn = s_img + (oi + kin) * IMS + kjn;
        float a[8], b[8];
#pragma unroll
        for (int t = 0; t < 8; ++t) { a[t] = rm[t]; b[t] = rn[t]; }

#pragma unroll
        for (int oj = 0; oj < 57; ++oj) {
            const float am0 = a[(oj    ) & 7], am1 = a[(oj + 1) & 7];
            const float am2 = a[(oj + 2) & 7], am3 = a[(oj + 3) & 7];
            const float bn0 = b[(oj    ) & 7], bn1 = b[(oj + 1) & 7];
            const float bn2 = b[(oj + 2) & 7], bn3 = b[(oj + 3) & 7];

            acc[0][0] = fmaf(am0, bn0, acc[0][0]);
            acc[0][1] = fmaf(am0, bn1, acc[0][1]);
            acc[0][2] = fmaf(am0, bn2, acc[0][2]);
            acc[0][3] = fmaf(am0, bn3, acc[0][3]);
            acc[1][0] = fmaf(am1, bn0, acc[1][0]);
            acc[1][1] = fmaf(am1, bn1, acc[1][1]);
            acc[1][2] = fmaf(am1, bn2, acc[1][2]);
            acc[1][3] = fmaf(am1, bn3, acc[1][3]);
            acc[2][0] = fmaf(am2, bn0, acc[2][0]);
            acc[2][1] = fmaf(am2, bn1, acc[2][1]);
            acc[2][2] = fmaf(am2, bn2, acc[2][2]);
            acc[2][3] = fmaf(am2, bn3, acc[2][3]);
            acc[3][0] = fmaf(am3, bn0, acc[3][0]);
            acc[3][1] = fmaf(am3, bn1, acc[3][1]);
            acc[3][2] = fmaf(am3, bn2, acc[3][2]);
            acc[3][3] = fmaf(am3, bn3, acc[3][3]);

            if (oj + 8 <= 59) {          // indices 8..59 needed; compile-time
                a[oj & 7] = rm[oj + 8];
                b[oj & 7] = rn[oj + 8];
            }
        }
    }

#pragma unroll
    for (int i = 0; i < 4; ++i)
#pragma unroll
        for (int j = 0; j < 4; ++j)
            s_corr[(m0 + i) * IMS + (n0 + j)] = acc[i][j];
    __syncthreads();

    if (tid < 64) {
        float g = s_corr[tid * IMS + tid];
        s_norm[tid] = 1.0f / fmaxf(sqrtf(g), 1e-12f);
    }
    __syncthreads();

#pragma unroll
    for (int i = 0; i < 4; ++i)
#pragma unroll
        for (int j = 0; j < 4; ++j)
            s_corr[(m0 + i) * IMS + (n0 + j)] =
                acc[i][j] * s_norm[m0 + i] * s_norm[n0 + j] * (1.0f / (float)NP);
    __syncthreads();

    // rank-by-count selection per column n (exact: ties broken by index)
    const int n   = tid & 63;
    const int sub = tid >> 6;
    for (int mi = 0; mi < 16; ++mi) {
        const int m = sub * 16 + mi;
        const float v = s_corr[m * IMS + n];
        int rank = 0;
#pragma unroll 8
        for (int mm = 0; mm < 64; ++mm) {
            float w = s_corr[mm * IMS + n];
            rank += (w > v) || (w == v && mm < m);
        }
#pragma unroll
        for (int r = 0; r < 9; ++r)
            if (rank == c_ranks2[r])
                g_pool2t[((size_t)bb * POOL_P + (r * 64 + n)) * 64 + cc] = v;
    }
}

// ---------------------------------------------------------------------------
// Stage 2a: per-(b,p) inverse norms over c.
// ---------------------------------------------------------------------------
__global__ void invn_kernel()
{
    int idx = blockIdx.x * blockDim.x + threadIdx.x;
    if (idx >= 8 * POOL_P) return;
    const float4* v = (const float4*)(g_pool2t + (size_t)idx * 64);
    float s = 0.0f;
#pragma unroll
    for (int i = 0; i < 16; ++i) {
        float4 t = v[i];
        s += t.x * t.x + t.y * t.y + t.z * t.z + t.w * t.w;
    }
    g_invn[idx] = 1.0f / fmaxf(sqrtf(s), 1e-12f);
}

// ---------------------------------------------------------------------------
// Stage 2b: one block per (b, group-of-4 q). Compute 4 columns of corr2 and
// bitonic-sort all 4 columns CONCURRENTLY (64 threads per column, 55 syncs
// total instead of 220). Direct pair enumeration: 8 active pairs/thread/step.
// ---------------------------------------------------------------------------
__global__ __launch_bounds__(256) void stage2_kernel(float* __restrict__ out)
{
    __shared__ float s_xq[4][64];
    __shared__ float s_buf[4][1024];

    const int tid = threadIdx.x;
    const int b   = blockIdx.x / 144;
    const int q0  = (blockIdx.x % 144) * 4;

    {   // load 4 q vectors (256 threads = 4*64 exactly)
        int k = tid >> 6, c = tid & 63;
        s_xq[k][c] = g_pool2t[((size_t)b * POOL_P + q0 + k) * 64 + c];
    }
    __syncthreads();

    // columns of corr2 (invn_p folded in; invn_q/64 applied after the sort —
    // positive scale preserves order). Pad to 1024 with -FLT_MAX.
    for (int p = tid; p < 1024; p += 256) {
        if (p < POOL_P) {
            const float4* xp = (const float4*)(g_pool2t + ((size_t)b * POOL_P + p) * 64);
            float d0 = 0.f, d1 = 0.f, d2 = 0.f, d3 = 0.f;
#pragma unroll
            for (int c4 = 0; c4 < 16; ++c4) {
                float4 v = xp[c4];
                int c = c4 * 4;
                d0 = fmaf(v.x, s_xq[0][c], d0); d0 = fmaf(v.y, s_xq[0][c+1], d0);
                d0 = fmaf(v.z, s_xq[0][c+2], d0); d0 = fmaf(v.w, s_xq[0][c+3], d0);
                d1 = fmaf(v.x, s_xq[1][c], d1); d1 = fmaf(v.y, s_xq[1][c+1], d1);
                d1 = fmaf(v.z, s_xq[1][c+2], d1); d1 = fmaf(v.w, s_xq[1][c+3], d1);
                d2 = fmaf(v.x, s_xq[2][c], d2); d2 = fmaf(v.y, s_xq[2][c+1], d2);
                d2 = fmaf(v.z, s_xq[2][c+2], d2); d2 = fmaf(v.w, s_xq[2][c+3], d2);
                d3 = fmaf(v.x, s_xq[3][c], d3); d3 = fmaf(v.y, s_xq[3][c+1], d3);
                d3 = fmaf(v.z, s_xq[3][c+2], d3); d3 = fmaf(v.w, s_xq[3][c+3], d3);
            }
            const float ip = g_invn[b * POOL_P + p];
            s_buf[0][p] = d0 * ip;
            s_buf[1][p] = d1 * ip;
            s_buf[2][p] = d2 * ip;
            s_buf[3][p] = d3 * ip;
        } else {
#pragma unroll
            for (int k = 0; k < 4; ++k) s_buf[k][p] = -3.402823466e38f;
        }
    }
    __syncthreads();

    // bitonic sort, descending; all 4 columns in lockstep
    {
        float* buf = s_buf[tid >> 6];
        const int u = tid & 63;
        for (int kk = 2; kk <= 1024; kk <<= 1) {
            for (int j = kk >> 1; j > 0; j >>= 1) {
                const int lo = j - 1;
#pragma unroll 4
                for (int t = u; t < 512; t += 64) {
                    int i   = ((t & ~lo) << 1) | (t & lo);   // (i & j) == 0
                    int ixj = i | j;
                    float a = buf[i], c2 = buf[ixj];
                    bool dsc = (i & kk) == 0;
                    if (dsc ? (a < c2) : (a > c2)) {
                        buf[i]   = c2;
                        buf[ixj] = a;
                    }
                }
                __syncthreads();
            }
        }
    }

    const double step = 574.0 / 114.0;   // np.linspace(1, 575, 115) step
    for (int idx = tid; idx < 4 * OUT_R; idx += 256) {
        int r = idx >> 2, k = idx & 3;
        int rank = (int)rint(1.0 + (double)r * step);  // half-even == np.round
        float invq = g_invn[b * POOL_P + q0 + k];
        out[((size_t)b * OUT_R + r) * POOL_P + (q0 + k)] =
            s_buf[k][rank] * invq * (1.0f / 64.0f);
    }
}

// ---------------------------------------------------------------------------
extern "C" void kernel_launch(void* const* d_in, const int* in_sizes, int n_in,
                              void* d_out, int out_size)
{
    const float* x = (const float*)d_in[0];
    float* out = (float*)d_out;

    stage1_kernel<<<N_BC, 256>>>(x);
    invn_kernel<<<(8 * POOL_P + 255) / 256, 256>>>();
    stage2_kernel<<<8 * 144, 256>>>(out);
}

// round 4
// speedup vs baseline: 1.8949x; 1.2334x over previous
#include <cuda_runtime.h>
#include <cuda_bf16.h>
#include <math.h>
#include <float.h>

// ---------------------------------------------------------------------------
// Self_Correlation_Per_tt : x[8,64,64,64] fp32 -> out[8,115,24,24] fp32
// ---------------------------------------------------------------------------

#define IMS 65          // padded shared row stride (floats)
#define N_BC 512        // 8 * 64
#define NP 3249         // 57*57 patch positions
#define POOL_P 576      // 9*64
#define OUT_R 115

typedef unsigned long long ull;

__device__ __align__(16) float g_pool2t[8 * POOL_P * 64];  // [b][p][c]
__device__ float g_invn[8 * POOL_P];                        // 1/max(||.||,eps)

__constant__ int c_ranks2[9] = {1, 9, 16, 24, 32, 40, 48, 55, 63};

// ---- packed fp32x2 helpers (sm_100+ PTX) ----------------------------------
__device__ __forceinline__ ull pack2(float lo, float hi) {
    ull r;
    asm("mov.b64 %0, {%1, %2};"
        : "=l"(r) : "r"(__float_as_uint(lo)), "r"(__float_as_uint(hi)));
    return r;
}
__device__ __forceinline__ void ffma2(ull& d, ull a, ull b) {
    asm("fma.rn.f32x2 %0, %1, %2, %0;" : "+l"(d) : "l"(a), "l"(b));
}
__device__ __forceinline__ float sum2(ull v) {
    unsigned int lo, hi;
    asm("mov.b64 {%0, %1}, %2;" : "=r"(lo), "=r"(hi) : "l"(v));
    return __uint_as_float(lo) + __uint_as_float(hi);
}

// ---------------------------------------------------------------------------
// Stage 1: one block per (b,c). 256 threads, 4x4 output tile each.
// Two oi rows processed per step via packed fma.rn.f32x2 (2x FLOP/instr).
// ---------------------------------------------------------------------------
__global__ __launch_bounds__(256) void stage1_kernel(const float* __restrict__ x)
{
    __shared__ float s_img[64 * IMS];
    __shared__ float s_corr[64 * IMS];
    __shared__ float s_norm[64];

    const int tid = threadIdx.x;
    const int blk = blockIdx.x;            // b*64 + c
    const int bb  = blk >> 6;
    const int cc  = blk & 63;

    const float* src = x + (size_t)blk * 4096;
    for (int i = tid; i < 4096; i += 256)
        s_img[(i >> 6) * IMS + (i & 63)] = src[i];
    __syncthreads();

    const int ty = tid >> 4, tx = tid & 15;
    const int m0 = ty * 4,   n0 = tx * 4;
    const int kim = ty >> 1, kjm = (ty & 1) * 4;   // m = ki*8+kj
    const int kin = tx >> 1, kjn = (tx & 1) * 4;

    ull acc2[4][4];
#pragma unroll
    for (int i = 0; i < 4; ++i)
#pragma unroll
        for (int j = 0; j < 4; ++j) acc2[i][j] = 0ull;   // (+0.f, +0.f)

    // ---- 28 row pairs: oi in {0,2,...,54} covering rows 0..55 ----
    for (int oi = 0; oi <= 54; oi += 2) {
        const float* rm0 = s_img + (oi + kim) * IMS + kjm;
        const float* rm1 = rm0 + IMS;
        const float* rn0 = s_img + (oi + kin) * IMS + kjn;
        const float* rn1 = rn0 + IMS;

        ull a_pk[8], b_pk[8];
#pragma unroll
        for (int t = 0; t < 8; ++t) {
            a_pk[t] = pack2(rm0[t], rm1[t]);
            b_pk[t] = pack2(rn0[t], rn1[t]);
        }

#pragma unroll
        for (int oj = 0; oj < 57; ++oj) {
            const ull am0 = a_pk[(oj    ) & 7], am1 = a_pk[(oj + 1) & 7];
            const ull am2 = a_pk[(oj + 2) & 7], am3 = a_pk[(oj + 3) & 7];
            const ull bn0 = b_pk[(oj    ) & 7], bn1 = b_pk[(oj + 1) & 7];
            const ull bn2 = b_pk[(oj + 2) & 7], bn3 = b_pk[(oj + 3) & 7];

            ffma2(acc2[0][0], am0, bn0); ffma2(acc2[0][1], am0, bn1);
            ffma2(acc2[0][2], am0, bn2); ffma2(acc2[0][3], am0, bn3);
            ffma2(acc2[1][0], am1, bn0); ffma2(acc2[1][1], am1, bn1);
            ffma2(acc2[1][2], am1, bn2); ffma2(acc2[1][3], am1, bn3);
            ffma2(acc2[2][0], am2, bn0); ffma2(acc2[2][1], am2, bn1);
            ffma2(acc2[2][2], am2, bn2); ffma2(acc2[2][3], am2, bn3);
            ffma2(acc2[3][0], am3, bn0); ffma2(acc2[3][1], am3, bn1);
            ffma2(acc2[3][2], am3, bn2); ffma2(acc2[3][3], am3, bn3);

            if (oj + 8 <= 59) {   // compile-time guard; positions up to 59
                a_pk[oj & 7] = pack2(rm0[oj + 8], rm1[oj + 8]);
                b_pk[oj & 7] = pack2(rn0[oj + 8], rn1[oj + 8]);
            }
        }
    }

    float acc[4][4];
#pragma unroll
    for (int i = 0; i < 4; ++i)
#pragma unroll
        for (int j = 0; j < 4; ++j) acc[i][j] = sum2(acc2[i][j]);

    // ---- scalar tail: oi = 56 ----
    {
        const float* rm = s_img + (56 + kim) * IMS + kjm;
        const float* rn = s_img + (56 + kin) * IMS + kjn;
        float a[8], b[8];
#pragma unroll
        for (int t = 0; t < 8; ++t) { a[t] = rm[t]; b[t] = rn[t]; }
#pragma unroll
        for (int oj = 0; oj < 57; ++oj) {
            const float am0 = a[(oj    ) & 7], am1 = a[(oj + 1) & 7];
            const float am2 = a[(oj + 2) & 7], am3 = a[(oj + 3) & 7];
            const float bn0 = b[(oj    ) & 7], bn1 = b[(oj + 1) & 7];
            const float bn2 = b[(oj + 2) & 7], bn3 = b[(oj + 3) & 7];
            acc[0][0] = fmaf(am0, bn0, acc[0][0]); acc[0][1] = fmaf(am0, bn1, acc[0][1]);
            acc[0][2] = fmaf(am0, bn2, acc[0][2]); acc[0][3] = fmaf(am0, bn3, acc[0][3]);
            acc[1][0] = fmaf(am1, bn0, acc[1][0]); acc[1][1] = fmaf(am1, bn1, acc[1][1]);
            acc[1][2] = fmaf(am1, bn2, acc[1][2]); acc[1][3] = fmaf(am1, bn3, acc[1][3]);
            acc[2][0] = fmaf(am2, bn0, acc[2][0]); acc[2][1] = fmaf(am2, bn1, acc[2][1]);
            acc[2][2] = fmaf(am2, bn2, acc[2][2]); acc[2][3] = fmaf(am2, bn3, acc[2][3]);
            acc[3][0] = fmaf(am3, bn0, acc[3][0]); acc[3][1] = fmaf(am3, bn1, acc[3][1]);
            acc[3][2] = fmaf(am3, bn2, acc[3][2]); acc[3][3] = fmaf(am3, bn3, acc[3][3]);
            if (oj + 8 <= 59) {
                a[oj & 7] = rm[oj + 8];
                b[oj & 7] = rn[oj + 8];
            }
        }
    }

#pragma unroll
    for (int i = 0; i < 4; ++i)
#pragma unroll
        for (int j = 0; j < 4; ++j)
            s_corr[(m0 + i) * IMS + (n0 + j)] = acc[i][j];
    __syncthreads();

    if (tid < 64) {
        float g = s_corr[tid * IMS + tid];
        s_norm[tid] = 1.0f / fmaxf(sqrtf(g), 1e-12f);
    }
    __syncthreads();

#pragma unroll
    for (int i = 0; i < 4; ++i)
#pragma unroll
        for (int j = 0; j < 4; ++j)
            s_corr[(m0 + i) * IMS + (n0 + j)] =
                acc[i][j] * s_norm[m0 + i] * s_norm[n0 + j] * (1.0f / (float)NP);
    __syncthreads();

    // rank-by-count selection per column n (exact: ties broken by index)
    const int n   = tid & 63;
    const int sub = tid >> 6;
    for (int mi = 0; mi < 16; ++mi) {
        const int m = sub * 16 + mi;
        const float v = s_corr[m * IMS + n];
        int rank = 0;
#pragma unroll 8
        for (int mm = 0; mm < 64; ++mm) {
            float w = s_corr[mm * IMS + n];
            rank += (w > v) || (w == v && mm < m);
        }
#pragma unroll
        for (int r = 0; r < 9; ++r)
            if (rank == c_ranks2[r])
                g_pool2t[((size_t)bb * POOL_P + (r * 64 + n)) * 64 + cc] = v;
    }
}

// ---------------------------------------------------------------------------
// Stage 2a: per-(b,p) inverse norms over c.
// ---------------------------------------------------------------------------
__global__ void invn_kernel()
{
    int idx = blockIdx.x * blockDim.x + threadIdx.x;
    if (idx >= 8 * POOL_P) return;
    const float4* v = (const float4*)(g_pool2t + (size_t)idx * 64);
    float s = 0.0f;
#pragma unroll
    for (int i = 0; i < 16; ++i) {
        float4 t = v[i];
        s += t.x * t.x + t.y * t.y + t.z * t.z + t.w * t.w;
    }
    g_invn[idx] = 1.0f / fmaxf(sqrtf(s), 1e-12f);
}

// ---------------------------------------------------------------------------
// Stage 2b: one block per (b, group-of-8 q). 8 warps; warp w computes and
// sorts column q0+w with a fully register-resident 1024-element bitonic
// network (32 values per lane; j>=32 steps are register min/max, j<=16 steps
// are one shfl.bfly + select each).
// ---------------------------------------------------------------------------
__global__ __launch_bounds__(256) void stage2_kernel(float* __restrict__ out)
{
    __shared__ float4 s_xq4[8][16];          // 8 q vectors, 64 ch each
    __shared__ float  s_cols[8][POOL_P];

    const int tid  = threadIdx.x;
    const int lane = tid & 31;
    const int w    = tid >> 5;               // warp id = column within group
    const int b    = blockIdx.x / 72;
    const int q0   = (blockIdx.x % 72) * 8;

    {   // load 8 q vectors (512 floats)
        float* sx = (float*)s_xq4;
        for (int i = tid; i < 512; i += 256) {
            int k = i >> 6, c = i & 63;
            sx[k * 64 + c] = g_pool2t[((size_t)b * POOL_P + q0 + k) * 64 + c];
        }
    }
    __syncthreads();

    // ---- columns of corr2 (invn_p folded; invn_q/64 applied post-sort) ----
    for (int p = tid; p < POOL_P; p += 256) {
        const float4* xp = (const float4*)(g_pool2t + ((size_t)b * POOL_P + p) * 64);
        float d[8];
#pragma unroll
        for (int k = 0; k < 8; ++k) d[k] = 0.0f;
#pragma unroll
        for (int c4 = 0; c4 < 16; ++c4) {
            float4 v = xp[c4];
#pragma unroll
            for (int k = 0; k < 8; ++k) {
                float4 q = s_xq4[k][c4];
                d[k] = fmaf(v.x, q.x, d[k]);
                d[k] = fmaf(v.y, q.y, d[k]);
                d[k] = fmaf(v.z, q.z, d[k]);
                d[k] = fmaf(v.w, q.w, d[k]);
            }
        }
        const float ip = g_invn[b * POOL_P + p];
#pragma unroll
        for (int k = 0; k < 8; ++k) s_cols[k][p] = d[k] * ip;
    }
    __syncthreads();

    // ---- register bitonic sort (descending), 1024 = 32 regs x 32 lanes ----
    // global index i = r*32 + lane
    float val[32];
#pragma unroll
    for (int r = 0; r < 32; ++r)
        val[r] = (r < 18) ? s_cols[w][r * 32 + lane] : -FLT_MAX;

#pragma unroll
    for (int s = 1; s <= 10; ++s) {
        const int kk = 1 << s;
#pragma unroll
        for (int jj = s - 1; jj >= 0; --jj) {
            const int j = 1 << jj;
            if (jj >= 5) {
                // register step: partner differs in register bit (j>>5)
                const int jr = j >> 5;
#pragma unroll
                for (int r = 0; r < 32; ++r) {
                    if ((r & jr) == 0) {
                        const int rp = r | jr;
                        const bool d = ((r & (kk >> 5)) == 0);   // s>=6 here
                        float hi = fmaxf(val[r], val[rp]);
                        float lo = fminf(val[r], val[rp]);
                        val[r]  = d ? hi : lo;
                        val[rp] = d ? lo : hi;
                    }
                }
            } else {
                // shuffle step: partner lane ^ j, same register slot
                const bool A = ((lane & j) == 0);
#pragma unroll
                for (int r = 0; r < 32; ++r) {
                    float v  = val[r];
                    float pv = __shfl_xor_sync(0xffffffffu, v, j);
                    bool d;
                    if (s <= 4)      d = ((lane & kk) == 0);       // lane bit
                    else if (s == 5) d = ((r & 1) == 0);           // reg bit 0
                    else             d = ((r & (kk >> 5)) == 0);   // reg bits
                    bool keep_max = (d == A);
                    val[r] = keep_max ? fmaxf(v, pv) : fminf(v, pv);
                }
            }
        }
    }

    // sorted descending: rank i lives at (r=i>>5, lane=i&31); ranks <= 575
#pragma unroll
    for (int r = 0; r < 18; ++r)
        s_cols[w][r * 32 + lane] = val[r];
    __syncthreads();

    const double step = 574.0 / 114.0;   // np.linspace(1, 575, 115) step
    for (int idx = tid; idx < 8 * OUT_R; idx += 256) {
        int k = idx & 7, rr = idx >> 3;
        int rank = (int)rint(1.0 + (double)rr * step);  // half-even == np.round
        float invq = g_invn[b * POOL_P + q0 + k];
        out[((size_t)b * OUT_R + rr) * POOL_P + (q0 + k)] =
            s_cols[k][rank] * invq * (1.0f / 64.0f);
    }
}

// ---------------------------------------------------------------------------
extern "C" void kernel_launch(void* const* d_in, const int* in_sizes, int n_in,
                              void* d_out, int out_size)
{
    const float* x = (const float*)d_in[0];
    float* out = (float*)d_out;

    stage1_kernel<<<N_BC, 256>>>(x);
    invn_kernel<<<(8 * POOL_P + 255) / 256, 256>>>();
    stage2_kernel<<<8 * 72, 256>>>(out);
}

// round 5
// speedup vs baseline: 3.4094x; 1.7993x over previous
#include <cuda_runtime.h>
#include <cuda_bf16.h>
#include <math.h>
#include <float.h>

// ---------------------------------------------------------------------------
// Self_Correlation_Per_tt : x[8,64,64,64] fp32 -> out[8,115,24,24] fp32
// Stage 1 via lag-product sliding box sums: O(lags*rows) instead of O(64^2*P).
// ---------------------------------------------------------------------------

#define IMS 68          // s_img stride (16B-aligned rows, conflict-free f4)
#define CMS 65          // s_corr stride
#define RMS 121         // R row stride (odd -> conflict-free column walks)
#define N_BC 512        // 8 * 64
#define NP 3249         // 57*57 patch positions
#define POOL_P 576      // 9*64
#define OUT_R 115

// dynamic smem: img | corr | R[4][64][RMS]
#define OFF_IMG  0
#define OFF_CORR (64 * IMS)
#define OFF_R    (OFF_CORR + 64 * CMS)
#define S1_SMEM_FLOATS (OFF_R + 4 * 64 * RMS)
#define S1_SMEM_BYTES  (S1_SMEM_FLOATS * 4)

__device__ __align__(16) float g_pool2t[8 * POOL_P * 64];  // [b][p][c]
__device__ float g_invn[8 * POOL_P];                        // 1/max(||.||,eps)

__constant__ int c_ranks2[9] = {1, 9, 16, 24, 32, 40, 48, 55, 63};

// ---------------------------------------------------------------------------
// Stage 1: one block per (b,c). 256 threads, 154KB dynamic smem.
// ---------------------------------------------------------------------------
__global__ __launch_bounds__(256) void stage1_kernel(const float* __restrict__ x)
{
    extern __shared__ float smem[];
    float* s_img  = smem + OFF_IMG;    // [64][IMS]
    float* s_corr = smem + OFF_CORR;   // [64][CMS]  raw G, then normalized
    float* s_R    = smem + OFF_R;      // [4][64][RMS]
    __shared__ float s_norm[64];

    const int tid = threadIdx.x;
    const int blk = blockIdx.x;        // b*64 + c
    const int bb  = blk >> 6;
    const int cc  = blk & 63;

    const float* src = x + (size_t)blk * 4096;
    for (int i = tid; i < 4096; i += 256)
        s_img[(i >> 6) * IMS + (i & 63)] = src[i];
    __syncthreads();

    const int g = tid >> 6;            // di group within round
    const int u = tid & 63;            // row

    for (int rnd = 0; rnd < 2; ++rnd) {
        const int di = rnd * 4 + g;

        // ---- phase A: horizontal sliding row sums for all 15 dj ----------
        if (u <= 63 - di) {
            float ra[64], rb[64];
            const float4* pa = (const float4*)(s_img + u * IMS);
            const float4* pb = (const float4*)(s_img + (u + di) * IMS);
#pragma unroll
            for (int t = 0; t < 16; ++t) {
                float4 va = pa[t];
                ra[4*t+0] = va.x; ra[4*t+1] = va.y; ra[4*t+2] = va.z; ra[4*t+3] = va.w;
                float4 vb = pb[t];
                rb[4*t+0] = vb.x; rb[4*t+1] = vb.y; rb[4*t+2] = vb.z; rb[4*t+3] = vb.w;
            }
            float* Rrow = s_R + (g * 64 + u) * RMS;
#pragma unroll
            for (int dj = -7; dj <= 7; ++dj) {
                const int bl = (dj < 0) ? -dj : 0;
                const int bh = (dj > 0) ? 7 - dj : 7;
                float acc = 0.0f;
#pragma unroll
                for (int v = bl; v <= bl + 56; ++v)
                    acc = fmaf(ra[v], rb[v + dj], acc);
                Rrow[(dj + 7) * 8 + bl] = acc;
#pragma unroll
                for (int b2 = bl + 1; b2 <= bh; ++b2) {
                    acc += ra[b2 + 56] * rb[b2 + 56 + dj]
                         - ra[b2 - 1]  * rb[b2 - 1 + dj];
                    Rrow[(dj + 7) * 8 + b2] = acc;
                }
            }
        }
        __syncthreads();

        // ---- phase B: vertical sliding sums -> G entries (+ symmetric) ---
        for (int task = tid; task < 480; task += 256) {
            const int g2  = task / 120;
            const int rem = task % 120;
            const int dj  = rem / 8 - 7;
            const int b2  = rem % 8;
            const int di2 = rnd * 4 + g2;
            const int bl  = (dj < 0) ? -dj : 0;
            const int bh  = (dj > 0) ? 7 - dj : 7;
            if (b2 < bl || b2 > bh) continue;
            if (di2 == 0 && dj < 0) continue;    // covered by symmetric write

            const float* Rcol = s_R + g2 * 64 * RMS + rem;
            float acc = 0.0f;
#pragma unroll
            for (int uu = 0; uu < 57; ++uu)
                acc += Rcol[uu * RMS];
            int m = b2;                      // a = 0
            int n = di2 * 8 + (b2 + dj);
            s_corr[m * CMS + n] = acc;
            s_corr[n * CMS + m] = acc;
#pragma unroll
            for (int a = 1; a <= 7; ++a) {
                if (a > 7 - di2) break;
                acc += Rcol[(a + 56) * RMS] - Rcol[(a - 1) * RMS];
                m = a * 8 + b2;
                n = (a + di2) * 8 + (b2 + dj);
                s_corr[m * CMS + n] = acc;
                s_corr[n * CMS + m] = acc;
            }
        }
        __syncthreads();
    }

    // ---- normalize: corr = G * invn_m * invn_n / P -----------------------
    if (tid < 64) {
        float gdiag = s_corr[tid * CMS + tid];
        s_norm[tid] = 1.0f / fmaxf(sqrtf(gdiag), 1e-12f);
    }
    __syncthreads();
    for (int i = tid; i < 4096; i += 256) {
        int m = i >> 6, n = i & 63;
        s_corr[m * CMS + n] *= s_norm[m] * s_norm[n] * (1.0f / (float)NP);
    }
    __syncthreads();

    // ---- rank-by-count selection per column n (ties broken by index) -----
    const int n   = tid & 63;
    const int sub = tid >> 6;
    for (int mi = 0; mi < 16; ++mi) {
        const int m = sub * 16 + mi;
        const float v = s_corr[m * CMS + n];
        int rank = 0;
#pragma unroll 8
        for (int mm = 0; mm < 64; ++mm) {
            float w = s_corr[mm * CMS + n];
            rank += (w > v) || (w == v && mm < m);
        }
#pragma unroll
        for (int r = 0; r < 9; ++r)
            if (rank == c_ranks2[r])
                g_pool2t[((size_t)bb * POOL_P + (r * 64 + n)) * 64 + cc] = v;
    }
}

// ---------------------------------------------------------------------------
// Stage 2a: per-(b,p) inverse norms over c.
// ---------------------------------------------------------------------------
__global__ void invn_kernel()
{
    int idx = blockIdx.x * blockDim.x + threadIdx.x;
    if (idx >= 8 * POOL_P) return;
    const float4* v = (const float4*)(g_pool2t + (size_t)idx * 64);
    float s = 0.0f;
#pragma unroll
    for (int i = 0; i < 16; ++i) {
        float4 t = v[i];
        s += t.x * t.x + t.y * t.y + t.z * t.z + t.w * t.w;
    }
    g_invn[idx] = 1.0f / fmaxf(sqrtf(s), 1e-12f);
}

// ---------------------------------------------------------------------------
// Stage 2b: one block per (b, group-of-8 q). Warp w sorts column q0+w with a
// register-resident 1024-element bitonic network.
// ---------------------------------------------------------------------------
__global__ __launch_bounds__(256) void stage2_kernel(float* __restrict__ out)
{
    __shared__ float4 s_xq4[8][16];          // 8 q vectors, 64 ch each
    __shared__ float  s_cols[8][POOL_P];

    const int tid  = threadIdx.x;
    const int lane = tid & 31;
    const int w    = tid >> 5;               // warp id = column within group
    const int b    = blockIdx.x / 72;
    const int q0   = (blockIdx.x % 72) * 8;

    {   // load 8 q vectors (512 floats)
        float* sx = (float*)s_xq4;
        for (int i = tid; i < 512; i += 256) {
            int k = i >> 6, c = i & 63;
            sx[k * 64 + c] = g_pool2t[((size_t)b * POOL_P + q0 + k) * 64 + c];
        }
    }
    __syncthreads();

    // ---- columns of corr2 (invn_p folded; invn_q/64 applied post-sort) ----
    for (int p = tid; p < POOL_P; p += 256) {
        const float4* xp = (const float4*)(g_pool2t + ((size_t)b * POOL_P + p) * 64);
        float d[8];
#pragma unroll
        for (int k = 0; k < 8; ++k) d[k] = 0.0f;
#pragma unroll
        for (int c4 = 0; c4 < 16; ++c4) {
            float4 v = xp[c4];
#pragma unroll
            for (int k = 0; k < 8; ++k) {
                float4 q = s_xq4[k][c4];
                d[k] = fmaf(v.x, q.x, d[k]);
                d[k] = fmaf(v.y, q.y, d[k]);
                d[k] = fmaf(v.z, q.z, d[k]);
                d[k] = fmaf(v.w, q.w, d[k]);
            }
        }
        const float ip = g_invn[b * POOL_P + p];
#pragma unroll
        for (int k = 0; k < 8; ++k) s_cols[k][p] = d[k] * ip;
    }
    __syncthreads();

    // ---- register bitonic sort (descending), 1024 = 32 regs x 32 lanes ----
    float val[32];
#pragma unroll
    for (int r = 0; r < 32; ++r)
        val[r] = (r < 18) ? s_cols[w][r * 32 + lane] : -FLT_MAX;

#pragma unroll
    for (int s = 1; s <= 10; ++s) {
        const int kk = 1 << s;
#pragma unroll
        for (int jj = s - 1; jj >= 0; --jj) {
            const int j = 1 << jj;
            if (jj >= 5) {
                const int jr = j >> 5;
#pragma unroll
                for (int r = 0; r < 32; ++r) {
                    if ((r & jr) == 0) {
                        const int rp = r | jr;
                        const bool d = ((r & (kk >> 5)) == 0);
                        float hi = fmaxf(val[r], val[rp]);
                        float lo = fminf(val[r], val[rp]);
                        val[r]  = d ? hi : lo;
                        val[rp] = d ? lo : hi;
                    }
                }
            } else {
                const bool A = ((lane & j) == 0);
#pragma unroll
                for (int r = 0; r < 32; ++r) {
                    float v  = val[r];
                    float pv = __shfl_xor_sync(0xffffffffu, v, j);
                    bool d;
                    if (s <= 4)      d = ((lane & kk) == 0);
                    else if (s == 5) d = ((r & 1) == 0);
                    else             d = ((r & (kk >> 5)) == 0);
                    bool keep_max = (d == A);
                    val[r] = keep_max ? fmaxf(v, pv) : fminf(v, pv);
                }
            }
        }
    }

#pragma unroll
    for (int r = 0; r < 18; ++r)
        s_cols[w][r * 32 + lane] = val[r];
    __syncthreads();

    const double step = 574.0 / 114.0;   // np.linspace(1, 575, 115) step
    for (int idx = tid; idx < 8 * OUT_R; idx += 256) {
        int k = idx & 7, rr = idx >> 3;
        int rank = (int)rint(1.0 + (double)rr * step);  // half-even == np.round
        float invq = g_invn[b * POOL_P + q0 + k];
        out[((size_t)b * OUT_R + rr) * POOL_P + (q0 + k)] =
            s_cols[k][rank] * invq * (1.0f / 64.0f);
    }
}

// ---------------------------------------------------------------------------
extern "C" void kernel_launch(void* const* d_in, const int* in_sizes, int n_in,
                              void* d_out, int out_size)
{
    const float* x = (const float*)d_in[0];
    float* out = (float*)d_out;

    cudaFuncSetAttribute(stage1_kernel,
                         cudaFuncAttributeMaxDynamicSharedMemorySize,
                         S1_SMEM_BYTES);
    stage1_kernel<<<N_BC, 256, S1_SMEM_BYTES>>>(x);
    invn_kernel<<<(8 * POOL_P + 255) / 256, 256>>>();
    stage2_kernel<<<8 * 72, 256>>>(out);
}

// round 6
// speedup vs baseline: 6.5646x; 1.9254x over previous
#include <cuda_runtime.h>
#include <cuda_bf16.h>
#include <math.h>
#include <float.h>

// ---------------------------------------------------------------------------
// Self_Correlation_Per_tt : x[8,64,64,64] fp32 -> out[8,115,24,24] fp32
// Stage 1 via lag-product sliding box sums. Stage 2: c-major pool buffer,
// coalesced dots, lane-major register bitonic sort (15 shfl steps).
// ---------------------------------------------------------------------------

#define IMS 68          // s_img stride
#define CMS 65          // s_corr stride
#define RMS 121         // R row stride
#define N_BC 512        // 8 * 64
#define NP 3249         // 57*57 patch positions
#define POOL_P 576      // 9*64
#define OUT_R 115

#define OFF_IMG  0
#define OFF_CORR (64 * IMS)
#define OFF_R    (OFF_CORR + 64 * CMS)
#define S1_SMEM_FLOATS (OFF_R + 4 * 64 * RMS)
#define S1_SMEM_BYTES  (S1_SMEM_FLOATS * 4)

// c-major: [b][c][p]
__device__ __align__(16) float g_pool2t[8 * 64 * POOL_P];
__device__ float g_invn[8 * POOL_P];

__constant__ int c_ranks2[9] = {1, 9, 16, 24, 32, 40, 48, 55, 63};

// XOR bank swizzle for 1024-grid indices (bijective within each 32-block)
__device__ __forceinline__ int ph(int i) {
    return (i & ~31) | ((i ^ (i >> 5)) & 31);
}

// ---------------------------------------------------------------------------
// Stage 1: one block per (b,c). 256 threads, 154KB dynamic smem.
// ---------------------------------------------------------------------------
__global__ __launch_bounds__(256) void stage1_kernel(const float* __restrict__ x)
{
    extern __shared__ float smem[];
    float* s_img  = smem + OFF_IMG;
    float* s_corr = smem + OFF_CORR;
    float* s_R    = smem + OFF_R;
    __shared__ float s_norm[64];

    const int tid = threadIdx.x;
    const int blk = blockIdx.x;        // b*64 + c
    const int bb  = blk >> 6;
    const int cc  = blk & 63;

    const float* src = x + (size_t)blk * 4096;
    for (int i = tid; i < 4096; i += 256)
        s_img[(i >> 6) * IMS + (i & 63)] = src[i];
    __syncthreads();

    const int g = tid >> 6;
    const int u = tid & 63;

    for (int rnd = 0; rnd < 2; ++rnd) {
        const int di = rnd * 4 + g;

        if (u <= 63 - di) {
            float ra[64], rb[64];
            const float4* pa = (const float4*)(s_img + u * IMS);
            const float4* pb = (const float4*)(s_img + (u + di) * IMS);
#pragma unroll
            for (int t = 0; t < 16; ++t) {
                float4 va = pa[t];
                ra[4*t+0] = va.x; ra[4*t+1] = va.y; ra[4*t+2] = va.z; ra[4*t+3] = va.w;
                float4 vb = pb[t];
                rb[4*t+0] = vb.x; rb[4*t+1] = vb.y; rb[4*t+2] = vb.z; rb[4*t+3] = vb.w;
            }
            float* Rrow = s_R + (g * 64 + u) * RMS;
#pragma unroll
            for (int dj = -7; dj <= 7; ++dj) {
                const int bl = (dj < 0) ? -dj : 0;
                const int bh = (dj > 0) ? 7 - dj : 7;
                float acc = 0.0f;
#pragma unroll
                for (int v = bl; v <= bl + 56; ++v)
                    acc = fmaf(ra[v], rb[v + dj], acc);
                Rrow[(dj + 7) * 8 + bl] = acc;
#pragma unroll
                for (int b2 = bl + 1; b2 <= bh; ++b2) {
                    acc += ra[b2 + 56] * rb[b2 + 56 + dj]
                         - ra[b2 - 1]  * rb[b2 - 1 + dj];
                    Rrow[(dj + 7) * 8 + b2] = acc;
                }
            }
        }
        __syncthreads();

        for (int task = tid; task < 480; task += 256) {
            const int g2  = task / 120;
            const int rem = task % 120;
            const int dj  = rem / 8 - 7;
            const int b2  = rem % 8;
            const int di2 = rnd * 4 + g2;
            const int bl  = (dj < 0) ? -dj : 0;
            const int bh  = (dj > 0) ? 7 - dj : 7;
            if (b2 < bl || b2 > bh) continue;
            if (di2 == 0 && dj < 0) continue;

            const float* Rcol = s_R + g2 * 64 * RMS + rem;
            float acc = 0.0f;
#pragma unroll
            for (int uu = 0; uu < 57; ++uu)
                acc += Rcol[uu * RMS];
            int m = b2;
            int n = di2 * 8 + (b2 + dj);
            s_corr[m * CMS + n] = acc;
            s_corr[n * CMS + m] = acc;
#pragma unroll
            for (int a = 1; a <= 7; ++a) {
                if (a > 7 - di2) break;
                acc += Rcol[(a + 56) * RMS] - Rcol[(a - 1) * RMS];
                m = a * 8 + b2;
                n = (a + di2) * 8 + (b2 + dj);
                s_corr[m * CMS + n] = acc;
                s_corr[n * CMS + m] = acc;
            }
        }
        __syncthreads();
    }

    if (tid < 64) {
        float gdiag = s_corr[tid * CMS + tid];
        s_norm[tid] = 1.0f / fmaxf(sqrtf(gdiag), 1e-12f);
    }
    __syncthreads();
    for (int i = tid; i < 4096; i += 256) {
        int m = i >> 6, n = i & 63;
        s_corr[m * CMS + n] *= s_norm[m] * s_norm[n] * (1.0f / (float)NP);
    }
    __syncthreads();

    // rank-by-count selection per column n; write c-major pool buffer
    const int n   = tid & 63;
    const int sub = tid >> 6;
    float* dstc = g_pool2t + ((size_t)(bb * 64 + cc)) * POOL_P;
    for (int mi = 0; mi < 16; ++mi) {
        const int m = sub * 16 + mi;
        const float v = s_corr[m * CMS + n];
        int rank = 0;
#pragma unroll 8
        for (int mm = 0; mm < 64; ++mm) {
            float w = s_corr[mm * CMS + n];
            rank += (w > v) || (w == v && mm < m);
        }
#pragma unroll
        for (int r = 0; r < 9; ++r)
            if (rank == c_ranks2[r])
                dstc[r * 64 + n] = v;           // coalesced across n
    }
}

// ---------------------------------------------------------------------------
// Stage 2a: per-(b,p) inverse norms over c (coalesced over p).
// ---------------------------------------------------------------------------
__global__ void invn_kernel()
{
    int idx = blockIdx.x * blockDim.x + threadIdx.x;
    if (idx >= 8 * POOL_P) return;
    const int b = idx / POOL_P, p = idx % POOL_P;
    const float* base = g_pool2t + (size_t)b * 64 * POOL_P + p;
    float s = 0.0f;
#pragma unroll
    for (int c = 0; c < 64; ++c) {
        float v = base[c * POOL_P];
        s = fmaf(v, v, s);
    }
    g_invn[idx] = 1.0f / fmaxf(sqrtf(s), 1e-12f);
}

// ---------------------------------------------------------------------------
// Bitonic steps, layout i = lane*32 + r (compile-time register indices).
// ---------------------------------------------------------------------------
template<int S, int JJ>
__device__ __forceinline__ void bstep_reg(float (&val)[32], int lane)
{
    constexpr int J = 1 << JJ;            // JJ <= 4
    bool dsc_rt = true;
    if (S >= 5 && S <= 9) dsc_rt = ((lane & (1 << (S - 5))) == 0);
#pragma unroll
    for (int r = 0; r < 32; ++r) {
        if ((r & J) == 0) {
            const int rp = r | J;
            bool dsc;
            if (S <= 4) dsc = ((r & (1 << S)) == 0);
            else        dsc = dsc_rt;
            float hi = fmaxf(val[r], val[rp]);
            float lo = fminf(val[r], val[rp]);
            val[r]  = dsc ? hi : lo;
            val[rp] = dsc ? lo : hi;
        }
    }
}

template<int S, int JJ>
__device__ __forceinline__ void bstep_shfl(float (&val)[32], int lane)
{
    constexpr int L = 1 << (JJ - 5);      // JJ >= 5, S >= 6
    const bool A = ((lane & L) == 0);
    bool dsc = true;
    if (S <= 9) dsc = ((lane & (1 << (S - 5))) == 0);
    const bool keep_max = (dsc == A);
#pragma unroll
    for (int r = 0; r < 32; ++r) {
        float pv = __shfl_xor_sync(0xffffffffu, val[r], L);
        val[r] = keep_max ? fmaxf(val[r], pv) : fminf(val[r], pv);
    }
}

// ---------------------------------------------------------------------------
// Stage 2b: one block per (b, 8 q). Warp w sorts column q0+w.
// ---------------------------------------------------------------------------
__global__ __launch_bounds__(256) void stage2_kernel(float* __restrict__ out)
{
    __shared__ float4 s_xq4[8][16];          // 8 q vectors x 64 ch
    __shared__ float  s_cols[8][POOL_P];     // swizzled via ph()

    const int tid  = threadIdx.x;
    const int lane = tid & 31;
    const int w    = tid >> 5;
    const int b    = blockIdx.x / 72;
    const int q0   = (blockIdx.x % 72) * 8;

    const float* poolb = g_pool2t + (size_t)b * 64 * POOL_P;

    {   // load 8 q vectors
        float* sx = (float*)s_xq4;
        for (int i = tid; i < 512; i += 256) {
            int k = i >> 6, c = i & 63;
            sx[k * 64 + c] = poolb[(size_t)c * POOL_P + (q0 + k)];
        }
    }
    __syncthreads();

    // ---- dot phase: thread handles p = tid, tid+256, tid+512 -------------
    {
        float d[3][8];
#pragma unroll
        for (int pi = 0; pi < 3; ++pi)
#pragma unroll
            for (int k = 0; k < 8; ++k) d[pi][k] = 0.0f;

#pragma unroll 4
        for (int c4 = 0; c4 < 16; ++c4) {
            float4 q[8];
#pragma unroll
            for (int k = 0; k < 8; ++k) q[k] = s_xq4[k][c4];
            const float* xb = poolb + (size_t)(c4 * 4) * POOL_P;
#pragma unroll
            for (int pi = 0; pi < 3; ++pi) {
                const int p = tid + pi * 256;
                if (p < POOL_P) {
                    float x0 = xb[p];
                    float x1 = xb[POOL_P + p];
                    float x2 = xb[2 * POOL_P + p];
                    float x3 = xb[3 * POOL_P + p];
#pragma unroll
                    for (int k = 0; k < 8; ++k) {
                        d[pi][k] = fmaf(x0, q[k].x, d[pi][k]);
                        d[pi][k] = fmaf(x1, q[k].y, d[pi][k]);
                        d[pi][k] = fmaf(x2, q[k].z, d[pi][k]);
                        d[pi][k] = fmaf(x3, q[k].w, d[pi][k]);
                    }
                }
            }
        }
#pragma unroll
        for (int pi = 0; pi < 3; ++pi) {
            const int p = tid + pi * 256;
            if (p < POOL_P) {
                const float ip = g_invn[b * POOL_P + p];
                const int pp = ph(p);
#pragma unroll
                for (int k = 0; k < 8; ++k)
                    s_cols[k][pp] = d[pi][k] * ip;
            }
        }
    }
    __syncthreads();

    // ---- register bitonic sort, i = lane*32 + r; conflict-free loads -----
    float val[32];
#pragma unroll
    for (int r = 0; r < 32; ++r)
        val[r] = (lane < 18) ? s_cols[w][lane * 32 + ((r ^ lane) & 31)]
                             : -FLT_MAX;

    bstep_reg<1,0>(val, lane);
    bstep_reg<2,1>(val, lane); bstep_reg<2,0>(val, lane);
    bstep_reg<3,2>(val, lane); bstep_reg<3,1>(val, lane); bstep_reg<3,0>(val, lane);
    bstep_reg<4,3>(val, lane); bstep_reg<4,2>(val, lane); bstep_reg<4,1>(val, lane); bstep_reg<4,0>(val, lane);
    bstep_reg<5,4>(val, lane); bstep_reg<5,3>(val, lane); bstep_reg<5,2>(val, lane); bstep_reg<5,1>(val, lane); bstep_reg<5,0>(val, lane);
    bstep_shfl<6,5>(val, lane);
    bstep_reg<6,4>(val, lane); bstep_reg<6,3>(val, lane); bstep_reg<6,2>(val, lane); bstep_reg<6,1>(val, lane); bstep_reg<6,0>(val, lane);
    bstep_shfl<7,6>(val, lane); bstep_shfl<7,5>(val, lane);
    bstep_reg<7,4>(val, lane); bstep_reg<7,3>(val, lane); bstep_reg<7,2>(val, lane); bstep_reg<7,1>(val, lane); bstep_reg<7,0>(val, lane);
    bstep_shfl<8,7>(val, lane); bstep_shfl<8,6>(val, lane); bstep_shfl<8,5>(val, lane);
    bstep_reg<8,4>(val, lane); bstep_reg<8,3>(val, lane); bstep_reg<8,2>(val, lane); bstep_reg<8,1>(val, lane); bstep_reg<8,0>(val, lane);
    bstep_shfl<9,8>(val, lane); bstep_shfl<9,7>(val, lane); bstep_shfl<9,6>(val, lane); bstep_shfl<9,5>(val, lane);
    bstep_reg<9,4>(val, lane); bstep_reg<9,3>(val, lane); bstep_reg<9,2>(val, lane); bstep_reg<9,1>(val, lane); bstep_reg<9,0>(val, lane);
    bstep_shfl<10,9>(val, lane); bstep_shfl<10,8>(val, lane); bstep_shfl<10,7>(val, lane); bstep_shfl<10,6>(val, lane); bstep_shfl<10,5>(val, lane);
    bstep_reg<10,4>(val, lane); bstep_reg<10,3>(val, lane); bstep_reg<10,2>(val, lane); bstep_reg<10,1>(val, lane); bstep_reg<10,0>(val, lane);

    // write back sorted (descending): rank i = lane*32 + r; ranks <= 575
    if (lane < 18) {
#pragma unroll
        for (int r = 0; r < 32; ++r)
            s_cols[w][lane * 32 + ((r ^ lane) & 31)] = val[r];
    }
    __syncthreads();

    const double step = 574.0 / 114.0;   // np.linspace(1, 575, 115) step
    for (int idx = tid; idx < 8 * OUT_R; idx += 256) {
        int k = idx & 7, rr = idx >> 3;
        int rank = (int)rint(1.0 + (double)rr * step);  // half-even == np.round
        float invq = g_invn[b * POOL_P + q0 + k];
        out[((size_t)b * OUT_R + rr) * POOL_P + (q0 + k)] =
            s_cols[k][ph(rank)] * invq * (1.0f / 64.0f);
    }
}

// ---------------------------------------------------------------------------
extern "C" void kernel_launch(void* const* d_in, const int* in_sizes, int n_in,
                              void* d_out, int out_size)
{
    const float* x = (const float*)d_in[0];
    float* out = (float*)d_out;

    cudaFuncSetAttribute(stage1_kernel,
                         cudaFuncAttributeMaxDynamicSharedMemorySize,
                         S1_SMEM_BYTES);
    stage1_kernel<<<N_BC, 256, S1_SMEM_BYTES>>>(x);
    invn_kernel<<<(8 * POOL_P + 255) / 256, 256>>>();
    stage2_kernel<<<8 * 72, 256>>>(out);
}

// round 7
// speedup vs baseline: 8.0537x; 1.2268x over previous
#include <cuda_runtime.h>
#include <cuda_bf16.h>
#include <math.h>
#include <float.h>

// ---------------------------------------------------------------------------
// Self_Correlation_Per_tt : x[8,64,64,64] fp32 -> out[8,115,24,24] fp32
// Stage 1: lag-product sliding box sums, ILP-split accumulators, warp-sort
// ranking. Stage 2: c-major pool, coalesced dots, register bitonic sort.
// ---------------------------------------------------------------------------

#define IMS 68          // s_img stride
#define CMS 65          // s_corr stride
#define RMS 121         // R row stride
#define N_BC 512        // 8 * 64
#define NP 3249         // 57*57 patch positions
#define POOL_P 576      // 9*64
#define OUT_R 115

#define OFF_IMG  0
#define OFF_CORR (64 * IMS)
#define OFF_R    (OFF_CORR + 64 * CMS)
#define S1_SMEM_FLOATS (OFF_R + 4 * 64 * RMS)
#define S1_SMEM_BYTES  (S1_SMEM_FLOATS * 4)

// c-major: [b][c][p]
__device__ __align__(16) float g_pool2t[8 * 64 * POOL_P];
__device__ float g_invn[8 * POOL_P];

// XOR bank swizzle for 1024-grid indices
__device__ __forceinline__ int ph(int i) {
    return (i & ~31) | ((i ^ (i >> 5)) & 31);
}

// ---------------------------------------------------------------------------
// Stage 1: one block per (b,c). 256 threads, 154KB dynamic smem.
// ---------------------------------------------------------------------------
__global__ __launch_bounds__(256) void stage1_kernel(const float* __restrict__ x)
{
    extern __shared__ float smem[];
    float* s_img  = smem + OFF_IMG;
    float* s_corr = smem + OFF_CORR;
    float* s_R    = smem + OFF_R;
    __shared__ float s_norm[64];

    const int tid = threadIdx.x;
    const int blk = blockIdx.x;        // b*64 + c
    const int bb  = blk >> 6;
    const int cc  = blk & 63;

    const float* src = x + (size_t)blk * 4096;
    for (int i = tid; i < 4096; i += 256)
        s_img[(i >> 6) * IMS + (i & 63)] = src[i];
    __syncthreads();

    const int g = tid >> 6;
    const int u = tid & 63;

    for (int rnd = 0; rnd < 2; ++rnd) {
        const int di = rnd * 4 + g;

        // ---- phase A: horizontal sliding row sums, 4-way split dots ------
        if (u <= 63 - di) {
            float ra[64], rb[64];
            const float4* pa = (const float4*)(s_img + u * IMS);
            const float4* pb = (const float4*)(s_img + (u + di) * IMS);
#pragma unroll
            for (int t = 0; t < 16; ++t) {
                float4 va = pa[t];
                ra[4*t+0] = va.x; ra[4*t+1] = va.y; ra[4*t+2] = va.z; ra[4*t+3] = va.w;
                float4 vb = pb[t];
                rb[4*t+0] = vb.x; rb[4*t+1] = vb.y; rb[4*t+2] = vb.z; rb[4*t+3] = vb.w;
            }
            float* Rrow = s_R + (g * 64 + u) * RMS;
#pragma unroll
            for (int dj = -7; dj <= 7; ++dj) {
                const int bl = (dj < 0) ? -dj : 0;
                const int bh = (dj > 0) ? 7 - dj : 7;
                float a0 = 0.f, a1 = 0.f, a2 = 0.f, a3 = 0.f;
#pragma unroll
                for (int v = bl; v < bl + 56; v += 4) {
                    a0 = fmaf(ra[v],     rb[v + dj],     a0);
                    a1 = fmaf(ra[v + 1], rb[v + 1 + dj], a1);
                    a2 = fmaf(ra[v + 2], rb[v + 2 + dj], a2);
                    a3 = fmaf(ra[v + 3], rb[v + 3 + dj], a3);
                }
                float acc = ((a0 + a2) + (a1 + a3))
                          + ra[bl + 56] * rb[bl + 56 + dj];
                Rrow[(dj + 7) * 8 + bl] = acc;
#pragma unroll
                for (int b2 = bl + 1; b2 <= bh; ++b2) {
                    acc += ra[b2 + 56] * rb[b2 + 56 + dj]
                         - ra[b2 - 1]  * rb[b2 - 1 + dj];
                    Rrow[(dj + 7) * 8 + b2] = acc;
                }
            }
        }
        __syncthreads();

        // ---- phase B: vertical sliding sums, 4-way split -----------------
        for (int task = tid; task < 480; task += 256) {
            const int g2  = task / 120;
            const int rem = task % 120;
            const int dj  = rem / 8 - 7;
            const int b2  = rem % 8;
            const int di2 = rnd * 4 + g2;
            const int bl  = (dj < 0) ? -dj : 0;
            const int bh  = (dj > 0) ? 7 - dj : 7;
            if (b2 < bl || b2 > bh) continue;
            if (di2 == 0 && dj < 0) continue;

            const float* Rcol = s_R + g2 * 64 * RMS + rem;
            float a0 = 0.f, a1 = 0.f, a2 = 0.f, a3 = 0.f;
#pragma unroll
            for (int uu = 0; uu < 56; uu += 4) {
                a0 += Rcol[(uu    ) * RMS];
                a1 += Rcol[(uu + 1) * RMS];
                a2 += Rcol[(uu + 2) * RMS];
                a3 += Rcol[(uu + 3) * RMS];
            }
            float acc = ((a0 + a2) + (a1 + a3)) + Rcol[56 * RMS];
            int m = b2;
            int n = di2 * 8 + (b2 + dj);
            s_corr[m * CMS + n] = acc;
            s_corr[n * CMS + m] = acc;
#pragma unroll
            for (int a = 1; a <= 7; ++a) {
                if (a <= 7 - di2) {
                    acc += Rcol[(a + 56) * RMS] - Rcol[(a - 1) * RMS];
                    m = a * 8 + b2;
                    n = (a + di2) * 8 + (b2 + dj);
                    s_corr[m * CMS + n] = acc;
                    s_corr[n * CMS + m] = acc;
                }
            }
        }
        __syncthreads();
    }

    // ---- norms from the raw diagonal -------------------------------------
    if (tid < 64) {
        float gdiag = s_corr[tid * CMS + tid];
        s_norm[tid] = 1.0f / fmaxf(sqrtf(gdiag), 1e-12f);
    }
    __syncthreads();

    // ---- ranking: warp w bitonic-sorts columns w*8..w*8+7 (64 vals each) --
    {
        const int lane = tid & 31;
        const int w    = tid >> 5;
        float* dstc = g_pool2t + (size_t)(bb * 64 + cc) * POOL_P;
        const float invP = 1.0f / (float)NP;
        const float nm0 = s_norm[lane] * invP;
        const float nm1 = s_norm[lane + 32] * invP;

        float v0[8], v1[8];
#pragma unroll
        for (int ci = 0; ci < 8; ++ci) {
            const int n = w * 8 + ci;
            const float sn = s_norm[n];
            v0[ci] = s_corr[lane * CMS + n] * nm0 * sn;          // i = lane
            v1[ci] = s_corr[(lane + 32) * CMS + n] * nm1 * sn;   // i = lane+32
        }

        // bitonic sort descending over i = lane + 32*r
#pragma unroll
        for (int s = 1; s <= 5; ++s) {
            const int kk = 1 << s;
#pragma unroll
            for (int j = (1 << (s - 1)); j >= 1; j >>= 1) {
#pragma unroll
                for (int ci = 0; ci < 8; ++ci) {
                    const bool A = ((lane & j) == 0);
                    bool d0, d1;
                    if (s < 5) { d0 = ((lane & kk) == 0); d1 = d0; }
                    else       { d0 = true; d1 = false; }
                    float p0 = __shfl_xor_sync(0xffffffffu, v0[ci], j);
                    v0[ci] = ((d0 == A) ? fmaxf(v0[ci], p0) : fminf(v0[ci], p0));
                    float p1 = __shfl_xor_sync(0xffffffffu, v1[ci], j);
                    v1[ci] = ((d1 == A) ? fmaxf(v1[ci], p1) : fminf(v1[ci], p1));
                }
            }
        }
        // stage s=6: j=32 cross-register step (dsc = true everywhere)
#pragma unroll
        for (int ci = 0; ci < 8; ++ci) {
            float hi = fmaxf(v0[ci], v1[ci]);
            float lo = fminf(v0[ci], v1[ci]);
            v0[ci] = hi; v1[ci] = lo;
        }
#pragma unroll
        for (int j = 16; j >= 1; j >>= 1) {
#pragma unroll
            for (int ci = 0; ci < 8; ++ci) {
                const bool A = ((lane & j) == 0);
                float p0 = __shfl_xor_sync(0xffffffffu, v0[ci], j);
                v0[ci] = A ? fmaxf(v0[ci], p0) : fminf(v0[ci], p0);
                float p1 = __shfl_xor_sync(0xffffffffu, v1[ci], j);
                v1[ci] = A ? fmaxf(v1[ci], p1) : fminf(v1[ci], p1);
            }
        }

        // emit ranks {1,9,16,24} from v0 (i=lane), {32,40,48,55,63} from v1
#pragma unroll
        for (int ci = 0; ci < 8; ++ci) {
            const int n = w * 8 + ci;
            if (lane == 1)  dstc[0 * 64 + n] = v0[ci];
            if (lane == 9)  dstc[1 * 64 + n] = v0[ci];
            if (lane == 16) dstc[2 * 64 + n] = v0[ci];
            if (lane == 24) dstc[3 * 64 + n] = v0[ci];
            if (lane == 0)  dstc[4 * 64 + n] = v1[ci];
            if (lane == 8)  dstc[5 * 64 + n] = v1[ci];
            if (lane == 16) dstc[6 * 64 + n] = v1[ci];
            if (lane == 23) dstc[7 * 64 + n] = v1[ci];
            if (lane == 31) dstc[8 * 64 + n] = v1[ci];
        }
    }
}

// ---------------------------------------------------------------------------
// Stage 2a: per-(b,p) inverse norms over c (coalesced over p).
// ---------------------------------------------------------------------------
__global__ void invn_kernel()
{
    int idx = blockIdx.x * blockDim.x + threadIdx.x;
    if (idx >= 8 * POOL_P) return;
    const int b = idx / POOL_P, p = idx % POOL_P;
    const float* base = g_pool2t + (size_t)b * 64 * POOL_P + p;
    float s0 = 0.f, s1 = 0.f, s2 = 0.f, s3 = 0.f;
#pragma unroll
    for (int c = 0; c < 64; c += 4) {
        float x0 = base[(c    ) * POOL_P];
        float x1 = base[(c + 1) * POOL_P];
        float x2 = base[(c + 2) * POOL_P];
        float x3 = base[(c + 3) * POOL_P];
        s0 = fmaf(x0, x0, s0); s1 = fmaf(x1, x1, s1);
        s2 = fmaf(x2, x2, s2); s3 = fmaf(x3, x3, s3);
    }
    float s = (s0 + s2) + (s1 + s3);
    g_invn[idx] = 1.0f / fmaxf(sqrtf(s), 1e-12f);
}

// ---------------------------------------------------------------------------
// Bitonic steps, layout i = lane*32 + r (compile-time register indices).
// ---------------------------------------------------------------------------
template<int S, int JJ>
__device__ __forceinline__ void bstep_reg(float (&val)[32], int lane)
{
    constexpr int J = 1 << JJ;            // JJ <= 4
    bool dsc_rt = true;
    if (S >= 5 && S <= 9) dsc_rt = ((lane & (1 << (S - 5))) == 0);
#pragma unroll
    for (int r = 0; r < 32; ++r) {
        if ((r & J) == 0) {
            const int rp = r | J;
            bool dsc;
            if (S <= 4) dsc = ((r & (1 << S)) == 0);
            else        dsc = dsc_rt;
            float hi = fmaxf(val[r], val[rp]);
            float lo = fminf(val[r], val[rp]);
            val[r]  = dsc ? hi : lo;
            val[rp] = dsc ? lo : hi;
        }
    }
}

template<int S, int JJ>
__device__ __forceinline__ void bstep_shfl(float (&val)[32], int lane)
{
    constexpr int L = 1 << (JJ - 5);      // JJ >= 5, S >= 6
    const bool A = ((lane & L) == 0);
    bool dsc = true;
    if (S <= 9) dsc = ((lane & (1 << (S - 5))) == 0);
    const bool keep_max = (dsc == A);
#pragma unroll
    for (int r = 0; r < 32; ++r) {
        float pv = __shfl_xor_sync(0xffffffffu, val[r], L);
        val[r] = keep_max ? fmaxf(val[r], pv) : fminf(val[r], pv);
    }
}

// ---------------------------------------------------------------------------
// Stage 2b: one block per (b, 8 q). Warp w sorts column q0+w.
// ---------------------------------------------------------------------------
__global__ __launch_bounds__(256) void stage2_kernel(float* __restrict__ out)
{
    __shared__ float4 s_xq4[8][16];          // 8 q vectors x 64 ch
    __shared__ float  s_cols[8][POOL_P];     // swizzled via ph()

    const int tid  = threadIdx.x;
    const int lane = tid & 31;
    const int w    = tid >> 5;
    const int b    = blockIdx.x / 72;
    const int q0   = (blockIdx.x % 72) * 8;

    const float* poolb = g_pool2t + (size_t)b * 64 * POOL_P;

    {   // load 8 q vectors
        float* sx = (float*)s_xq4;
        for (int i = tid; i < 512; i += 256) {
            int k = i >> 6, c = i & 63;
            sx[k * 64 + c] = poolb[(size_t)c * POOL_P + (q0 + k)];
        }
    }
    __syncthreads();

    // ---- dot phase: thread handles p = tid, tid+256, tid+512 -------------
    {
        float d[3][8];
#pragma unroll
        for (int pi = 0; pi < 3; ++pi)
#pragma unroll
            for (int k = 0; k < 8; ++k) d[pi][k] = 0.0f;

#pragma unroll 4
        for (int c4 = 0; c4 < 16; ++c4) {
            float4 q[8];
#pragma unroll
            for (int k = 0; k < 8; ++k) q[k] = s_xq4[k][c4];
            const float* xb = poolb + (size_t)(c4 * 4) * POOL_P;
#pragma unroll
            for (int pi = 0; pi < 3; ++pi) {
                const int p = tid + pi * 256;
                if (p < POOL_P) {
                    float x0 = xb[p];
                    float x1 = xb[POOL_P + p];
                    float x2 = xb[2 * POOL_P + p];
                    float x3 = xb[3 * POOL_P + p];
#pragma unroll
                    for (int k = 0; k < 8; ++k) {
                        d[pi][k] = fmaf(x0, q[k].x, d[pi][k]);
                        d[pi][k] = fmaf(x1, q[k].y, d[pi][k]);
                        d[pi][k] = fmaf(x2, q[k].z, d[pi][k]);
                        d[pi][k] = fmaf(x3, q[k].w, d[pi][k]);
                    }
                }
            }
        }
#pragma unroll
        for (int pi = 0; pi < 3; ++pi) {
            const int p = tid + pi * 256;
            if (p < POOL_P) {
                const float ip = g_invn[b * POOL_P + p];
                const int pp = ph(p);
#pragma unroll
                for (int k = 0; k < 8; ++k)
                    s_cols[k][pp] = d[pi][k] * ip;
            }
        }
    }
    __syncthreads();

    // ---- register bitonic sort, i = lane*32 + r; conflict-free loads -----
    float val[32];
#pragma unroll
    for (int r = 0; r < 32; ++r)
        val[r] = (lane < 18) ? s_cols[w][lane * 32 + ((r ^ lane) & 31)]
                             : -FLT_MAX;

    bstep_reg<1,0>(val, lane);
    bstep_reg<2,1>(val, lane); bstep_reg<2,0>(val, lane);
    bstep_reg<3,2>(val, lane); bstep_reg<3,1>(val, lane); bstep_reg<3,0>(val, lane);
    bstep_reg<4,3>(val, lane); bstep_reg<4,2>(val, lane); bstep_reg<4,1>(val, lane); bstep_reg<4,0>(val, lane);
    bstep_reg<5,4>(val, lane); bstep_reg<5,3>(val, lane); bstep_reg<5,2>(val, lane); bstep_reg<5,1>(val, lane); bstep_reg<5,0>(val, lane);
    bstep_shfl<6,5>(val, lane);
    bstep_reg<6,4>(val, lane); bstep_reg<6,3>(val, lane); bstep_reg<6,2>(val, lane); bstep_reg<6,1>(val, lane); bstep_reg<6,0>(val, lane);
    bstep_shfl<7,6>(val, lane); bstep_shfl<7,5>(val, lane);
    bstep_reg<7,4>(val, lane); bstep_reg<7,3>(val, lane); bstep_reg<7,2>(val, lane); bstep_reg<7,1>(val, lane); bstep_reg<7,0>(val, lane);
    bstep_shfl<8,7>(val, lane); bstep_shfl<8,6>(val, lane); bstep_shfl<8,5>(val, lane);
    bstep_reg<8,4>(val, lane); bstep_reg<8,3>(val, lane); bstep_reg<8,2>(val, lane); bstep_reg<8,1>(val, lane); bstep_reg<8,0>(val, lane);
    bstep_shfl<9,8>(val, lane); bstep_shfl<9,7>(val, lane); bstep_shfl<9,6>(val, lane); bstep_shfl<9,5>(val, lane);
    bstep_reg<9,4>(val, lane); bstep_reg<9,3>(val, lane); bstep_reg<9,2>(val, lane); bstep_reg<9,1>(val, lane); bstep_reg<9,0>(val, lane);
    bstep_shfl<10,9>(val, lane); bstep_shfl<10,8>(val, lane); bstep_shfl<10,7>(val, lane); bstep_shfl<10,6>(val, lane); bstep_shfl<10,5>(val, lane);
    bstep_reg<10,4>(val, lane); bstep_reg<10,3>(val, lane); bstep_reg<10,2>(val, lane); bstep_reg<10,1>(val, lane); bstep_reg<10,0>(val, lane);

    if (lane < 18) {
#pragma unroll
        for (int r = 0; r < 32; ++r)
            s_cols[w][lane * 32 + ((r ^ lane) & 31)] = val[r];
    }
    __syncthreads();

    const double step = 574.0 / 114.0;   // np.linspace(1, 575, 115) step
    for (int idx = tid; idx < 8 * OUT_R; idx += 256) {
        int k = idx & 7, rr = idx >> 3;
        int rank = (int)rint(1.0 + (double)rr * step);  // half-even == np.round
        float invq = g_invn[b * POOL_P + q0 + k];
        out[((size_t)b * OUT_R + rr) * POOL_P + (q0 + k)] =
            s_cols[k][ph(rank)] * invq * (1.0f / 64.0f);
    }
}

// ---------------------------------------------------------------------------
extern "C" void kernel_launch(void* const* d_in, const int* in_sizes, int n_in,
                              void* d_out, int out_size)
{
    const float* x = (const float*)d_in[0];
    float* out = (float*)d_out;

    cudaFuncSetAttribute(stage1_kernel,
                         cudaFuncAttributeMaxDynamicSharedMemorySize,
                         S1_SMEM_BYTES);
    stage1_kernel<<<N_BC, 256, S1_SMEM_BYTES>>>(x);
    invn_kernel<<<(8 * POOL_P + 255) / 256, 256>>>();
    stage2_kernel<<<8 * 72, 256>>>(out);
}